// round 6
// baseline (speedup 1.0000x reference)
#include <cuda_runtime.h>
#include <cuda_bf16.h>
#include <math.h>

#define SEQ   512
#define BATCH 64
#define DIM   512
#define G4    2048
#define NT    8
#define HD    64
#define TL    64
#define NACT  72
#define MROWS (SEQ*BATCH)

__device__ float g_xg [(size_t)MROWS*G4];
__device__ float g_val[(size_t)MROWS*DIM];
__device__ float g_act[(size_t)MROWS*NACT];
__device__ float g_ro [(size_t)MROWS*DIM];
__device__ __nv_bfloat16 g_hbh[2][BATCH*DIM];   // h hi plane, [buf][b][k]
__device__ __nv_bfloat16 g_hbl[2][BATCH*DIM];   // h lo plane
__device__ unsigned g_bar;

__device__ __forceinline__ float sigf(float x){ return 1.f/(1.f+__expf(-x)); }

__device__ __forceinline__ void cp16(void* dst_smem, const void* src){
  unsigned d = (unsigned)__cvta_generic_to_shared(dst_smem);
  asm volatile("cp.async.ca.shared.global [%0], [%1], 16;\n" :: "r"(d), "l"(src));
}
#define CP_COMMIT() asm volatile("cp.async.commit_group;\n" ::: "memory")
#define CP_WAIT(n)  asm volatile("cp.async.wait_group %0;\n" :: "n"(n) : "memory")

__global__ void init_kernel(){
  unsigned i = blockIdx.x*256u + threadIdx.x;
  if (i==0) g_bar = 0u;
  if (i < DIM*BATCH){
    g_hbh[0][i] = __float2bfloat16(0.f);
    g_hbl[0][i] = __float2bfloat16(0.f);
  }
}

// ================= bf16-split tensor GEMM (validated) ========================
#define GSTRIDE 24

__device__ __forceinline__ void cvt_store(__nv_bfloat16* Hp, __nv_bfloat16* Lp, float4 v){
  __nv_bfloat16 h0=__float2bfloat16(v.x), h1=__float2bfloat16(v.y);
  __nv_bfloat16 h2=__float2bfloat16(v.z), h3=__float2bfloat16(v.w);
  __nv_bfloat16 l0=__float2bfloat16(v.x-__bfloat162float(h0));
  __nv_bfloat16 l1=__float2bfloat16(v.y-__bfloat162float(h1));
  __nv_bfloat16 l2=__float2bfloat16(v.z-__bfloat162float(h2));
  __nv_bfloat16 l3=__float2bfloat16(v.w-__bfloat162float(h3));
  ((__nv_bfloat162*)Hp)[0] = __nv_bfloat162(h0,h1);
  ((__nv_bfloat162*)Hp)[1] = __nv_bfloat162(h2,h3);
  ((__nv_bfloat162*)Lp)[0] = __nv_bfloat162(l0,l1);
  ((__nv_bfloat162*)Lp)[1] = __nv_bfloat162(l2,l3);
}

#define MMA16816(C, A, B) \
  asm volatile("mma.sync.aligned.m16n8k16.row.col.f32.bf16.bf16.f32 " \
    "{%0,%1,%2,%3}, {%4,%5,%6,%7}, {%8,%9}, {%0,%1,%2,%3};" \
    : "+f"((C)[0]),"+f"((C)[1]),"+f"((C)[2]),"+f"((C)[3]) \
    : "r"((A)[0]),"r"((A)[1]),"r"((A)[2]),"r"((A)[3]), "r"((B)[0]),"r"((B)[1]))

#define LDSM4(R, addr) \
  asm volatile("ldmatrix.sync.aligned.m8n8.x4.shared.b16 {%0,%1,%2,%3}, [%4];" \
    : "=r"((R)[0]),"=r"((R)[1]),"=r"((R)[2]),"=r"((R)[3]) : "r"(addr))

#define LDSM2(R, addr) \
  asm volatile("ldmatrix.sync.aligned.m8n8.x2.shared.b16 {%0,%1}, [%2];" \
    : "=r"((R)[0]),"=r"((R)[1]) : "r"(addr))

__launch_bounds__(256)
__global__ void tgemm_bias(const float* __restrict__ A, const float* __restrict__ W,
                           const float* __restrict__ b1, const float* __restrict__ b2,
                           float* __restrict__ C, int N, int K)
{
  __shared__ __nv_bfloat16 sm[2][4][128*GSTRIDE];
  const int tid = threadIdx.x;
  const int lane = tid & 31, warp = tid >> 5;
  const int warpM = (warp>>2)*64, warpN = (warp&3)*32;
  const int ctaM = blockIdx.y*128, ctaN = blockIdx.x*128;

  float acc[4][4][4];
#pragma unroll
  for (int mf=0;mf<4;mf++)
#pragma unroll
    for (int nf=0;nf<4;nf++)
#pragma unroll
      for (int i=0;i<4;i++) acc[mf][nf][i]=0.f;

  const float* Abase = A + (size_t)ctaM*K;
  const float* Wbase = W + (size_t)ctaN*K;
  const int r0 = tid>>2, kq = tid&3;
  const int sts_off = r0*GSTRIDE + kq*4;
  const int a_row = lane & 15, a_kh = (lane>>4)*8;
  const int b_row = lane & 7,  b_kh = ((lane>>3)&1)*8;

  unsigned smem_u32[2][4];
#pragma unroll
  for (int bf=0;bf<2;bf++)
#pragma unroll
    for (int q=0;q<4;q++) smem_u32[bf][q] = (unsigned)__cvta_generic_to_shared(sm[bf][q]);

  float4 ra0, ra1, rw0, rw1;
  ra0 = *(const float4*)(Abase + (size_t)r0*K + kq*4);
  ra1 = *(const float4*)(Abase + (size_t)(r0+64)*K + kq*4);
  rw0 = *(const float4*)(Wbase + (size_t)r0*K + kq*4);
  rw1 = *(const float4*)(Wbase + (size_t)(r0+64)*K + kq*4);
  cvt_store(&sm[0][0][sts_off],              &sm[0][1][sts_off],              ra0);
  cvt_store(&sm[0][0][sts_off+64*GSTRIDE],   &sm[0][1][sts_off+64*GSTRIDE],   ra1);
  cvt_store(&sm[0][2][sts_off],              &sm[0][3][sts_off],              rw0);
  cvt_store(&sm[0][2][sts_off+64*GSTRIDE],   &sm[0][3][sts_off+64*GSTRIDE],   rw1);
  __syncthreads();

  const int nchunk = K/16;
  for (int kc = 0; kc < nchunk; kc++){
    const int buf = kc & 1;
    if (kc+1 < nchunk){
      const float* ap = Abase + (kc+1)*16;
      const float* wp = Wbase + (kc+1)*16;
      ra0 = *(const float4*)(ap + (size_t)r0*K + kq*4);
      ra1 = *(const float4*)(ap + (size_t)(r0+64)*K + kq*4);
      rw0 = *(const float4*)(wp + (size_t)r0*K + kq*4);
      rw1 = *(const float4*)(wp + (size_t)(r0+64)*K + kq*4);
    }
    unsigned bh[4][2], bl[4][2];
#pragma unroll
    for (int nf=0;nf<4;nf++){
      unsigned off = (unsigned)((warpN + nf*8 + b_row)*GSTRIDE + b_kh)*2u;
      LDSM2(bh[nf], smem_u32[buf][2] + off);
      LDSM2(bl[nf], smem_u32[buf][3] + off);
    }
#pragma unroll
    for (int mf=0;mf<4;mf++){
      unsigned aoff = (unsigned)((warpM + mf*16 + a_row)*GSTRIDE + a_kh)*2u;
      unsigned ah[4], al[4];
      LDSM4(ah, smem_u32[buf][0] + aoff);
      LDSM4(al, smem_u32[buf][1] + aoff);
#pragma unroll
      for (int nf=0;nf<4;nf++){
        MMA16816(acc[mf][nf], ah, bh[nf]);
        MMA16816(acc[mf][nf], ah, bl[nf]);
        MMA16816(acc[mf][nf], al, bh[nf]);
      }
    }
    if (kc+1 < nchunk){
      const int nb = buf^1;
      cvt_store(&sm[nb][0][sts_off],            &sm[nb][1][sts_off],            ra0);
      cvt_store(&sm[nb][0][sts_off+64*GSTRIDE], &sm[nb][1][sts_off+64*GSTRIDE], ra1);
      cvt_store(&sm[nb][2][sts_off],            &sm[nb][3][sts_off],            rw0);
      cvt_store(&sm[nb][2][sts_off+64*GSTRIDE], &sm[nb][3][sts_off+64*GSTRIDE], rw1);
    }
    __syncthreads();
  }

#pragma unroll
  for (int nf=0;nf<4;nf++){
    int col = ctaN + warpN + nf*8 + (lane&3)*2;
    float bb0 = b1[col]   + (b2 ? b2[col]   : 0.f);
    float bb1 = b1[col+1] + (b2 ? b2[col+1] : 0.f);
#pragma unroll
    for (int mf=0;mf<4;mf++){
      int row = ctaM + warpM + mf*16 + (lane>>2);
      *(float2*)(C + (size_t)row*N + col)     = make_float2(acc[mf][nf][0]+bb0, acc[mf][nf][1]+bb1);
      *(float2*)(C + (size_t)(row+8)*N + col) = make_float2(acc[mf][nf][2]+bb0, acc[mf][nf][3]+bb1);
    }
  }
}

// ---------- LSTM v4: tensor recurrence + fused actions ----------------------
// 128 CTAs x 256 thr. CTA: 16 gate rows x 64 batches x K=512 (MMA), plus
// actions slice (tp = blk&7, bg = blk>>3): 9 action rows x 4 batches, computed
// from the SMEM H tile in the barrier-wait shadow.
#define HST 520
#define WHI 0
#define WLO (16*HST)
#define HHI (32*HST)
#define HLO (96*HST)
#define REDOFF 41600                    // float idx after 160*520 bf16
#define WAOFF  (REDOFF + 2176)          // W_act slice: 9*512 fp32
#define BAOFF  (WAOFF + 4608)           // b_act slice: 9 fp32
#define LS4_SMEM ((BAOFF + 16)*4)

extern __shared__ float ls_smem[];

__launch_bounds__(256)
__global__ void lstm4_kernel(const float* __restrict__ W_hh,
                             const float* __restrict__ W_act,
                             const float* __restrict__ b_act)
{
  __nv_bfloat16* sb = (__nv_bfloat16*)ls_smem;
  float* red = ls_smem + REDOFF;
  float* was = ls_smem + WAOFF;
  float* sba = ls_smem + BAOFF;

  const int t = threadIdx.x, lane = t&31, w = t>>5;
  const int c0 = blockIdx.x*4;
  const int tp = blockIdx.x & 7, bg = blockIdx.x >> 3;
  const int mw = w&3, kh = w>>2;
  const int fj = t>>6, fb = t&63;
  const int a_row = lane & 15, a_kh2 = (lane>>4)*8;
  const int b_row = lane & 7,  b_kh2 = ((lane>>3)&1)*8;

  // resident W_hh slice (bf16 hi/lo)
  for (int id=t; id<16*512; id+=256){
    int row16 = id>>9, k = id&511;
    int gg = row16>>2, jj = row16&3;
    float v = W_hh[(size_t)(gg*DIM + c0 + jj)*DIM + k];
    __nv_bfloat16 hv = __float2bfloat16(v);
    sb[WHI + row16*HST + k] = hv;
    sb[WLO + row16*HST + k] = __float2bfloat16(v - __bfloat162float(hv));
  }
  // resident W_act slice (fp32): rows tp*9..tp*9+8
  for (int id=t; id<9*512; id+=256){
    int a = id>>9, k = id&511;
    was[a*512 + k] = W_act[(size_t)(tp*9 + a)*DIM + k];
  }
  if (t < 9) sba[t] = b_act[tp*9 + t];
  float cstate = 0.f;
  __syncthreads();

  const unsigned sb_u = (unsigned)__cvta_generic_to_shared(sb);

  for (int s=0; s<=SEQ; s++){
    float x0,x1,x2,x3;
    if (s < SEQ){
      const float* xgp = g_xg + ((size_t)s*BATCH + fb)*G4 + c0 + fj;
      x0 = xgp[0]; x1 = xgp[DIM]; x2 = xgp[2*DIM]; x3 = xgp[3*DIM];
    }

    // H tile cp.async: 4 pipelined groups of 64 k-columns (hi+lo)
    {
      const __nv_bfloat16* srcH = g_hbh[s&1];
      const __nv_bfloat16* srcL = g_hbl[s&1];
#pragma unroll
      for (int g2=0; g2<4; g2++){
#pragma unroll
        for (int j=0;j<4;j++){
          int idx = j*32 + lane;          // 0..127
          int r = idx>>3, cc2 = idx&7;
          int kg = kh*256 + g2*64 + cc2*8;
          int row = mw*16 + r;
          cp16(sb + HHI + row*HST + kg, srcH + row*512 + kg);
          cp16(sb + HLO + row*HST + kg, srcL + row*512 + kg);
        }
        CP_COMMIT();
      }
    }

    if (s < SEQ){
      float acc[2][4];
#pragma unroll
      for (int nf=0;nf<2;nf++)
#pragma unroll
        for (int i=0;i<4;i++) acc[nf][i]=0.f;

#pragma unroll
      for (int ks=0; ks<16; ks++){
        if (ks==0){ CP_WAIT(3); __syncwarp(); }
        else if (ks==4){ CP_WAIT(2); __syncwarp(); }
        else if (ks==8){ CP_WAIT(1); __syncwarp(); }
        else if (ks==12){ CP_WAIT(0); __syncwarp(); }
        const int kbase = kh*256 + ks*16;
        unsigned ah[4], al[4];
        unsigned aoff = (unsigned)((HHI) + (mw*16 + a_row)*HST + kbase + a_kh2)*2u;
        unsigned loff = (unsigned)((HLO) + (mw*16 + a_row)*HST + kbase + a_kh2)*2u;
        LDSM4(ah, sb_u + aoff);
        LDSM4(al, sb_u + loff);
#pragma unroll
        for (int nf=0;nf<2;nf++){
          unsigned bh[2], bl[2];
          unsigned bo = (unsigned)((nf*8 + b_row)*HST + kbase + b_kh2)*2u;
          LDSM2(bh, sb_u + (unsigned)(WHI*2) + bo);
          LDSM2(bl, sb_u + (unsigned)(WLO*2) + bo);
          MMA16816(acc[nf], ah, bh);
          MMA16816(acc[nf], ah, bl);
          MMA16816(acc[nf], al, bh);
        }
      }

      // split-K reduce
#pragma unroll
      for (int nf=0;nf<2;nf++){
        int n0 = nf*8 + (lane&3)*2;
        int b0 = mw*16 + (lane>>2);
        red[(kh*16 + n0  )*68 + b0  ] = acc[nf][0];
        red[(kh*16 + n0+1)*68 + b0  ] = acc[nf][1];
        red[(kh*16 + n0  )*68 + b0+8] = acc[nf][2];
        red[(kh*16 + n0+1)*68 + b0+8] = acc[nf][3];
      }
      __syncthreads();   // also: all warps' H tiles now CTA-visible

      {
        float gi=x0, gf=x1, gg2=x2, go=x3;
#pragma unroll
        for (int k2=0;k2<2;k2++){
          gi  += red[(k2*16 +  0 + fj)*68 + fb];
          gf  += red[(k2*16 +  4 + fj)*68 + fb];
          gg2 += red[(k2*16 +  8 + fj)*68 + fb];
          go  += red[(k2*16 + 12 + fj)*68 + fb];
        }
        cstate = sigf(gf)*cstate + sigf(gi)*tanhf(gg2);
        float hv = sigf(go)*tanhf(cstate);
        __nv_bfloat16 hh = __float2bfloat16(hv);
        g_hbh[(s+1)&1][fb*512 + c0 + fj] = hh;
        g_hbl[(s+1)&1][fb*512 + c0 + fj] = __float2bfloat16(hv - __bfloat162float(hh));
      }
      __syncthreads();
      if (t==0){           // signal ASAP
        __threadfence();
        atomicAdd(&g_bar, 1u);
      }
    } else {
      CP_WAIT(0);
      __syncthreads();     // tail: full hidden[511] tile visible
    }

    // fused actions[s-1] from SMEM H tile (hi+lo), in the barrier-wait shadow
    if (s >= 1){
#pragma unroll
      for (int o = 0; o < 5; o++){
        int oo = w + o*8;
        if (oo < 36){
          int a = oo>>2, bi = oo&3;
          int b = bg*4 + bi;
          const __nv_bfloat162* hh2 = (const __nv_bfloat162*)(sb + HHI + b*HST + lane*16);
          const __nv_bfloat162* hl2 = (const __nv_bfloat162*)(sb + HLO + b*HST + lane*16);
          const float* wa = was + a*512 + lane*16;
          float sum = 0.f;
#pragma unroll
          for (int k=0;k<8;k++){
            float2 h2 = __bfloat1622float2(hh2[k]);
            float2 l2 = __bfloat1622float2(hl2[k]);
            sum += (h2.x+l2.x)*wa[2*k] + (h2.y+l2.y)*wa[2*k+1];
          }
#pragma unroll
          for (int off=16; off>0; off>>=1)
            sum += __shfl_xor_sync(0xffffffffu, sum, off);
          if (lane==0)
            g_act[((size_t)(s-1)*BATCH + b)*NACT + tp*9 + a] = sum + sba[a];
        }
      }
    }

    if (s < SEQ){
      if (t==0){
        unsigned target = (unsigned)(s+1)*128u;
        while (*(volatile unsigned*)&g_bar < target) { }
      }
      __syncthreads();
    }
  }
}

// NTM scan: 1 CTA per (batch,tape); thread c owns tape[:,c] in regs
__launch_bounds__(64)
__global__ void tape_kernel(float* __restrict__ out)
{
  __shared__ float wpos[TL], rpos[TL], rpr[TL];
  const int bb = blockIdx.x>>3, tp = blockIdx.x&7, c = threadIdx.x;
  float tape[TL];
#pragma unroll
  for (int l=0;l<TL;l++) tape[l]=0.f;
  wpos[c] = (c==0)?1.f:0.f;
  rpos[c] = (c==0)?1.f:0.f;
  __syncthreads();

  for (int s=0;s<SEQ;s++){
    const float* ap = g_act + ((size_t)s*BATCH + bb)*NACT + tp*9;
    float r0=ap[0], r1=ap[1], r2=ap[2];
    float w0=ap[3], w1=ap[4], w2=ap[5];
    float rw0=sigf(ap[6]), rw1=sigf(ap[7]), rw2=sigf(ap[8]);

    float mr = fmaxf(r0,fmaxf(r1,r2));
    float e0=__expf(r0-mr), e1=__expf(r1-mr), e2=__expf(r2-mr);
    float ir = 1.f/(e0+e1+e2);
    float rd0=e0*ir, rd1=e1*ir, rd2=e2*ir;
    float mw = fmaxf(w0,fmaxf(w1,w2));
    float f0=__expf(w0-mw), f1=__expf(w1-mw), f2=__expf(w2-mw);
    float iw = 1.f/(f0+f1+f2);
    float wd0=f0*iw, wd1=f1*iw, wd2=f2*iw;

    float v = g_val[((size_t)s*BATCH + bb)*DIM + tp*HD + c];

    float oldv = 0.f;
#pragma unroll
    for (int l=0;l<TL;l++) oldv += tape[l]*wpos[l];

    float nw = wpos[(c+1)&63]*wd0 + wpos[c]*wd1 + wpos[(c+63)&63]*wd2;
    float nr = rpos[(c+1)&63]*rd0 + rpos[c]*rd1 + rpos[(c+63)&63]*rd2;
    rpr[c] = rpos[c]*rw0;
    __syncthreads();

    float upd = v*rw1 - oldv*rw2;
    float ro = 0.f;
#pragma unroll
    for (int l=0;l<TL;l++){
      tape[l] += wpos[l]*upd;
      ro += tape[l]*rpr[l];
    }
    __syncthreads();
    wpos[c]=nw; rpos[c]=nr;
    g_ro[((size_t)s*BATCH + bb)*DIM + tp*HD + c] = ro;
    __syncthreads();
  }
#pragma unroll
  for (int l=0;l<TL;l++)
    out[(size_t)SEQ*BATCH*DIM + ((size_t)l*BATCH + bb)*DIM + tp*HD + c] = tape[l];
}

extern "C" void kernel_launch(void* const* d_in, const int* in_sizes, int n_in,
                              void* d_out, int out_size)
{
  const float* inputs = (const float*)d_in[0];
  const float* W_ih   = (const float*)d_in[1];
  const float* W_hh   = (const float*)d_in[2];
  const float* b_ih   = (const float*)d_in[3];
  const float* b_hh   = (const float*)d_in[4];
  const float* W_act  = (const float*)d_in[5];
  const float* b_act  = (const float*)d_in[6];
  const float* W_val  = (const float*)d_in[7];
  const float* b_val  = (const float*)d_in[8];
  const float* W_out  = (const float*)d_in[9];
  const float* b_out  = (const float*)d_in[10];
  float* out = (float*)d_out;

  float *xg_p, *val_p, *ro_p;
  cudaGetSymbolAddress((void**)&xg_p,  g_xg);
  cudaGetSymbolAddress((void**)&val_p, g_val);
  cudaGetSymbolAddress((void**)&ro_p,  g_ro);

  cudaFuncSetAttribute(lstm4_kernel, cudaFuncAttributeMaxDynamicSharedMemorySize, LS4_SMEM);

  init_kernel<<<128,256>>>();
  tgemm_bias<<<dim3(16,256),256>>>(inputs, W_ih, b_ih, b_hh, xg_p, G4, DIM);
  tgemm_bias<<<dim3(4,256),256>>>(inputs, W_val, b_val, nullptr, val_p, DIM, DIM);
  lstm4_kernel<<<128,256,LS4_SMEM>>>(W_hh, W_act, b_act);
  tape_kernel<<<512,64>>>(out);
  tgemm_bias<<<dim3(4,256),256>>>(ro_p, W_out, b_out, nullptr, out, DIM, DIM);
}